// round 6
// baseline (speedup 1.0000x reference)
#include <cuda_runtime.h>
#include <cuda_fp16.h>
#include <math.h>
#include <stdint.h>

#define N_NODES 50000
#define N_EDGES 800000
#define F0 128
#define F1 96
#define F2 96
#define F3 40

// ---------------- scratch (static device globals; no allocation) ----------------
__device__ int    g_deg[N_NODES];
__device__ int    g_cur[N_NODES];
__device__ int    g_off[N_NODES + 1];
__device__ int    g_csr[N_EDGES];
__device__ __half g_t1[(size_t)N_NODES * F1];   // x @ W1   (fp16)
__device__ float  g_h1[(size_t)N_NODES * F1];   // relu(agg(t1)+b1)
__device__ __half g_t2[(size_t)N_NODES * F2];   // h1 @ W2  (fp16)
__device__ float  g_h2[(size_t)N_NODES * F2];   // relu(agg(t2)+b2)
__device__ __half g_t3[(size_t)N_NODES * F3];   // h2 @ W3  (fp16)

// ---------------- inline edge-index dtype detection (int64 vs int32) ----------------
__device__ __forceinline__ int block_detect_is64(const int* __restrict__ ei, int* s_flag) {
    if (threadIdx.x < 32) {
        int acc = 0;
#pragma unroll
        for (int j = 0; j < 4; j++) acc |= ei[1 + 2 * (threadIdx.x * 4 + j)];
#pragma unroll
        for (int o = 16; o > 0; o >>= 1) acc |= __shfl_xor_sync(0xffffffffu, acc, o);
        if (threadIdx.x == 0) *s_flag = (acc == 0) ? 1 : 0;
    }
    __syncthreads();
    return *s_flag;
}

__device__ __forceinline__ int edge_src(const int* ei, int e, int is64) {
    return is64 ? ei[2 * e] : ei[e];
}
__device__ __forceinline__ int edge_dst(const int* ei, int e, int is64) {
    return is64 ? ei[2 * (N_EDGES + e)] : ei[N_EDGES + e];
}

// ---------------- CSR build ----------------
__global__ void zero_deg_kernel() {
    int i = blockIdx.x * blockDim.x + threadIdx.x;
    if (i < N_NODES) g_deg[i] = 0;
}

__global__ void hist_kernel(const int* __restrict__ ei) {
    __shared__ int s_is64;
    int is64 = block_detect_is64(ei, &s_is64);
    int e = blockIdx.x * blockDim.x + threadIdx.x;
    if (e >= N_EDGES) return;
    atomicAdd(&g_deg[edge_dst(ei, e, is64)], 1);
}

// single-kernel scan: 1 block x 1024 threads, blocked 49 elems/thread
__global__ void scan_kernel() {
    constexpr int CH = (N_NODES + 1023) / 1024;   // 49
    __shared__ int wsum[32];
    int t = threadIdx.x;
    int lane = t & 31, w = t >> 5;
    int base = t * CH;

    int s = 0;
#pragma unroll 7
    for (int j = 0; j < CH; j++) {
        int i = base + j;
        if (i < N_NODES) s += g_deg[i];
    }
    int incl = s;
#pragma unroll
    for (int o = 1; o < 32; o <<= 1) {
        int u = __shfl_up_sync(0xffffffffu, incl, o);
        if (lane >= o) incl += u;
    }
    if (lane == 31) wsum[w] = incl;
    __syncthreads();
    if (w == 0) {
        int v = wsum[lane];
#pragma unroll
        for (int o = 1; o < 32; o <<= 1) {
            int u = __shfl_up_sync(0xffffffffu, v, o);
            if (lane >= o) v += u;
        }
        wsum[lane] = v;
    }
    __syncthreads();
    int excl = incl - s + ((w > 0) ? wsum[w - 1] : 0);

    int run = excl;
#pragma unroll 7
    for (int j = 0; j < CH; j++) {
        int i = base + j;
        if (i < N_NODES) {
            int v = g_deg[i];
            g_cur[i] = run;
            run += v;
            g_off[i + 1] = run;
        }
    }
    if (t == 0) g_off[0] = 0;
}

__global__ void scatter_kernel(const int* __restrict__ ei) {
    __shared__ int s_is64;
    int is64 = block_detect_is64(ei, &s_is64);
    int e = blockIdx.x * blockDim.x + threadIdx.x;
    if (e >= N_EDGES) return;
    int d = edge_dst(ei, e, is64);
    int s = edge_src(ei, e, is64);
    int p = atomicAdd(&g_cur[d], 1);
    g_csr[p] = s;
}

// ---------------- 3xTF32 tensor-core GEMM: Y[M,N](fp16) = X[M,K](fp32) @ W[K,N] ----------------
__device__ __forceinline__ uint32_t f2tf32(float f) {
    uint32_t r;
    asm("cvt.rna.tf32.f32 %0, %1;" : "=r"(r) : "f"(f));
    return r;
}

__device__ __forceinline__ void mma8(float c[4], const uint32_t a[4],
                                     uint32_t b0, uint32_t b1) {
    asm volatile(
        "mma.sync.aligned.m16n8k8.row.col.f32.tf32.tf32.f32 "
        "{%0,%1,%2,%3}, {%4,%5,%6,%7}, {%8,%9}, {%0,%1,%2,%3};"
        : "+f"(c[0]), "+f"(c[1]), "+f"(c[2]), "+f"(c[3])
        : "r"(a[0]), "r"(a[1]), "r"(a[2]), "r"(a[3]), "r"(b0), "r"(b1));
}

template <int K, int N>
__global__ void __launch_bounds__(256) mma_gemm_kernel(
        const float* __restrict__ X, const float* __restrict__ W,
        __half* __restrict__ Y) {
    constexpr int NT  = N / 8;
    constexpr int PAD = (8 - (N % 32) + 32) % 32;
    constexpr int PS  = N + PAD;
    extern __shared__ uint32_t smem[];
    uint32_t* sHi = smem;
    uint32_t* sLo = smem + K * PS;

    int tid = threadIdx.x;
    for (int i = tid; i < K * N; i += 256) {
        int k = i / N, n = i % N;
        float w = __ldg(W + i);
        uint32_t hi = f2tf32(w);
        sHi[k * PS + n] = hi;
        sLo[k * PS + n] = f2tf32(w - __uint_as_float(hi));
    }
    __syncthreads();

    int warp = tid >> 5, lane = tid & 31;
    int tig = lane & 3, grp = lane >> 2;
    int row0 = blockIdx.x * 128 + warp * 16;
    int r0 = row0 + grp, r1 = row0 + grp + 8;
    const float* xr0 = X + (size_t)((r0 < N_NODES) ? r0 : (N_NODES - 1)) * K;
    const float* xr1 = X + (size_t)((r1 < N_NODES) ? r1 : (N_NODES - 1)) * K;

    float c[NT][4];
#pragma unroll
    for (int nt = 0; nt < NT; nt++)
#pragma unroll
        for (int j = 0; j < 4; j++) c[nt][j] = 0.f;

#pragma unroll 1
    for (int k0 = 0; k0 < K; k0 += 8) {
        float a0 = __ldg(xr0 + k0 + tig);
        float a1 = __ldg(xr1 + k0 + tig);
        float a2 = __ldg(xr0 + k0 + tig + 4);
        float a3 = __ldg(xr1 + k0 + tig + 4);
        uint32_t ahi[4] = {f2tf32(a0), f2tf32(a1), f2tf32(a2), f2tf32(a3)};
        uint32_t alo[4] = {f2tf32(a0 - __uint_as_float(ahi[0])),
                           f2tf32(a1 - __uint_as_float(ahi[1])),
                           f2tf32(a2 - __uint_as_float(ahi[2])),
                           f2tf32(a3 - __uint_as_float(ahi[3]))};
        const uint32_t* rHi0 = sHi + (k0 + tig) * PS + grp;
        const uint32_t* rHi1 = sHi + (k0 + tig + 4) * PS + grp;
        const uint32_t* rLo0 = sLo + (k0 + tig) * PS + grp;
        const uint32_t* rLo1 = sLo + (k0 + tig + 4) * PS + grp;
#pragma unroll
        for (int nt = 0; nt < NT; nt++) {
            uint32_t b0h = rHi0[nt * 8], b1h = rHi1[nt * 8];
            uint32_t b0l = rLo0[nt * 8], b1l = rLo1[nt * 8];
            mma8(c[nt], ahi, b0h, b1h);   // hi*hi
            mma8(c[nt], alo, b0h, b1h);   // lo*hi
            mma8(c[nt], ahi, b0l, b1l);   // hi*lo
        }
    }

#pragma unroll
    for (int nt = 0; nt < NT; nt++) {
        int col = nt * 8 + 2 * tig;
        if (r0 < N_NODES)
            *(__half2*)(Y + (size_t)r0 * N + col) = __floats2half2_rn(c[nt][0], c[nt][1]);
        if (r1 < N_NODES)
            *(__half2*)(Y + (size_t)r1 * N + col) = __floats2half2_rn(c[nt][2], c[nt][3]);
    }
}

// ---------------- gather aggregation (fp16 in, fp32 accum) + fused epilogue ----------------
// EPI 0: relu(acc + bias) -> fp32   EPI 1: log_softmax(acc + bias) -> fp32
template <int D, int EPI>
__global__ void agg_kernel(const __half* __restrict__ xin, const float* __restrict__ bias,
                           float* __restrict__ xout) {
    int gw   = (blockIdx.x * blockDim.x + threadIdx.x) >> 5;
    int lane = threadIdx.x & 31;
    if (gw >= N_NODES) return;
    constexpr int D4 = D / 4;
    float4 acc = make_float4(0.f, 0.f, 0.f, 0.f);
    int beg = g_off[gw], end = g_off[gw + 1];
    int e = beg;
    for (; e + 3 < end; e += 4) {
        int s0 = g_csr[e], s1 = g_csr[e + 1], s2 = g_csr[e + 2], s3 = g_csr[e + 3];
        if (lane < D4) {
            uint2 v0 = __ldg((const uint2*)(xin + (size_t)s0 * D) + lane);
            uint2 v1 = __ldg((const uint2*)(xin + (size_t)s1 * D) + lane);
            uint2 v2 = __ldg((const uint2*)(xin + (size_t)s2 * D) + lane);
            uint2 v3 = __ldg((const uint2*)(xin + (size_t)s3 * D) + lane);
#pragma unroll
            for (int j = 0; j < 4; j++) {
                uint2 v = (j == 0) ? v0 : (j == 1) ? v1 : (j == 2) ? v2 : v3;
                float2 f0 = __half22float2(*reinterpret_cast<__half2*>(&v.x));
                float2 f1 = __half22float2(*reinterpret_cast<__half2*>(&v.y));
                acc.x += f0.x; acc.y += f0.y; acc.z += f1.x; acc.w += f1.y;
            }
        }
    }
    for (; e < end; e++) {
        int s0 = g_csr[e];
        if (lane < D4) {
            uint2 v = __ldg((const uint2*)(xin + (size_t)s0 * D) + lane);
            float2 f0 = __half22float2(*reinterpret_cast<__half2*>(&v.x));
            float2 f1 = __half22float2(*reinterpret_cast<__half2*>(&v.y));
            acc.x += f0.x; acc.y += f0.y; acc.z += f1.x; acc.w += f1.y;
        }
    }
    float4 bb = (lane < D4) ? ((const float4*)bias)[lane] : make_float4(0.f, 0.f, 0.f, 0.f);
    acc.x += bb.x; acc.y += bb.y; acc.z += bb.z; acc.w += bb.w;

    if (EPI == 0) {
        if (lane < D4) {
            acc.x = fmaxf(acc.x, 0.f); acc.y = fmaxf(acc.y, 0.f);
            acc.z = fmaxf(acc.z, 0.f); acc.w = fmaxf(acc.w, 0.f);
            ((float4*)(xout + (size_t)gw * D))[lane] = acc;
        }
    } else {
        float m = (lane < D4)
                ? fmaxf(fmaxf(acc.x, acc.y), fmaxf(acc.z, acc.w))
                : -INFINITY;
#pragma unroll
        for (int o = 16; o > 0; o >>= 1) m = fmaxf(m, __shfl_xor_sync(0xffffffffu, m, o));
        float s = (lane < D4)
                ? (expf(acc.x - m) + expf(acc.y - m)) + (expf(acc.z - m) + expf(acc.w - m))
                : 0.f;
#pragma unroll
        for (int o = 16; o > 0; o >>= 1) s += __shfl_xor_sync(0xffffffffu, s, o);
        float l = m + logf(s);
        if (lane < D4) {
            acc.x -= l; acc.y -= l; acc.z -= l; acc.w -= l;
            ((float4*)(xout + (size_t)gw * D))[lane] = acc;
        }
    }
}

// ---------------- launch ----------------
extern "C" void kernel_launch(void* const* d_in, const int* in_sizes, int n_in,
                              void* d_out, int out_size) {
    const float* x  = (const float*)d_in[0];
    const float* W1 = (const float*)d_in[1];
    const float* b1 = (const float*)d_in[2];
    const float* W2 = (const float*)d_in[3];
    const float* b2 = (const float*)d_in[4];
    const float* W3 = (const float*)d_in[5];
    const float* b3 = (const float*)d_in[6];
    const int*   ei = (const int*)d_in[7];
    float* out = (float*)d_out;

    __half *p_t1, *p_t2, *p_t3;
    float *p_h1, *p_h2;
    cudaGetSymbolAddress((void**)&p_t1, g_t1);
    cudaGetSymbolAddress((void**)&p_h1, g_h1);
    cudaGetSymbolAddress((void**)&p_t2, g_t2);
    cudaGetSymbolAddress((void**)&p_h2, g_h2);
    cudaGetSymbolAddress((void**)&p_t3, g_t3);

    constexpr int PS1 = F1 + ((8 - (F1 % 32) + 32) % 32);   // 104
    constexpr int PS2 = F2 + ((8 - (F2 % 32) + 32) % 32);   // 104
    constexpr int PS3 = F3 + ((8 - (F3 % 32) + 32) % 32);   // 40
    const int smem1 = 2 * F0 * PS1 * 4;
    const int smem2 = 2 * F1 * PS2 * 4;
    const int smem3 = 2 * F2 * PS3 * 4;

    static cudaStream_t s2 = nullptr;
    static cudaEvent_t ev_fork = nullptr, ev_join = nullptr;
    if (!s2) {
        cudaStreamCreateWithFlags(&s2, cudaStreamNonBlocking);
        cudaEventCreateWithFlags(&ev_fork, cudaEventDisableTiming);
        cudaEventCreateWithFlags(&ev_join, cudaEventDisableTiming);
        cudaFuncSetAttribute(mma_gemm_kernel<F0, F1>,
                             cudaFuncAttributeMaxDynamicSharedMemorySize, smem1);
        cudaFuncSetAttribute(mma_gemm_kernel<F1, F2>,
                             cudaFuncAttributeMaxDynamicSharedMemorySize, smem2);
        cudaFuncSetAttribute(mma_gemm_kernel<F2, F3>,
                             cudaFuncAttributeMaxDynamicSharedMemorySize, smem3);
    }

    // fork: CSR build chain on s2, concurrent with GEMM1 on the main stream
    cudaEventRecord(ev_fork, 0);
    cudaStreamWaitEvent(s2, ev_fork, 0);

    zero_deg_kernel<<<(N_NODES + 255) / 256, 256, 0, s2>>>();
    hist_kernel<<<(N_EDGES + 255) / 256, 256, 0, s2>>>(ei);
    scan_kernel<<<1, 1024, 0, s2>>>();
    scatter_kernel<<<(N_EDGES + 255) / 256, 256, 0, s2>>>(ei);
    cudaEventRecord(ev_join, s2);

    const int agg_grid  = (N_NODES * 32 + 255) / 256;
    const int gemm_grid = (N_NODES + 127) / 128;

    // main stream: t1 = x @ W1 (independent of CSR)
    mma_gemm_kernel<F0, F1><<<gemm_grid, 256, smem1>>>(x, W1, p_t1);

    // join: aggregation needs CSR
    cudaStreamWaitEvent(0, ev_join, 0);

    // layer 1: h1 = relu(agg(t1) + b1)
    agg_kernel<F1, 0><<<agg_grid, 256>>>(p_t1, b1, p_h1);
    // layer 2
    mma_gemm_kernel<F1, F2><<<gemm_grid, 256, smem2>>>(p_h1, W2, p_t2);
    agg_kernel<F2, 0><<<agg_grid, 256>>>(p_t2, b2, p_h2);
    // layer 3 + log_softmax
    mma_gemm_kernel<F2, F3><<<gemm_grid, 256, smem3>>>(p_h2, W3, p_t3);
    agg_kernel<F3, 1><<<agg_grid, 256>>>(p_t3, b3, out);
}

// round 7
// speedup vs baseline: 1.7193x; 1.7193x over previous
#include <cuda_runtime.h>
#include <cuda_fp16.h>
#include <math.h>
#include <stdint.h>

#define N_NODES 50000
#define N_EDGES 800000
#define F0 128
#define F1 96
#define F2 96
#define F3 40
#define NB ((N_NODES + 1023) / 1024)   // 49 scan blocks

// ---------------- scratch (static device globals; no allocation) ----------------
__device__ int    g_deg[N_NODES];
__device__ int    g_cur[N_NODES];
__device__ int    g_off[N_NODES + 1];
__device__ int    g_csr[N_EDGES];
__device__ int    g_bsum[NB];
__device__ __half g_t1[(size_t)N_NODES * F1];   // x @ W1   (fp16)
__device__ float  g_h1[(size_t)N_NODES * F1];   // relu(agg(t1)+b1)
__device__ __half g_t2[(size_t)N_NODES * F2];   // h1 @ W2  (fp16)
__device__ float  g_h2[(size_t)N_NODES * F2];   // relu(agg(t2)+b2)
__device__ __half g_t3[(size_t)N_NODES * F3];   // h2 @ W3  (fp16)

// ---------------- inline edge-index dtype detection (int64 vs int32) ----------------
__device__ __forceinline__ int block_detect_is64(const int* __restrict__ ei, int* s_flag) {
    if (threadIdx.x < 32) {
        int acc = 0;
#pragma unroll
        for (int j = 0; j < 4; j++) acc |= ei[1 + 2 * (threadIdx.x * 4 + j)];
#pragma unroll
        for (int o = 16; o > 0; o >>= 1) acc |= __shfl_xor_sync(0xffffffffu, acc, o);
        if (threadIdx.x == 0) *s_flag = (acc == 0) ? 1 : 0;
    }
    __syncthreads();
    return *s_flag;
}

__device__ __forceinline__ int edge_src(const int* ei, int e, int is64) {
    return is64 ? ei[2 * e] : ei[e];
}
__device__ __forceinline__ int edge_dst(const int* ei, int e, int is64) {
    return is64 ? ei[2 * (N_EDGES + e)] : ei[N_EDGES + e];
}

// ---------------- CSR build ----------------
__global__ void zero_deg_kernel() {
    int i = blockIdx.x * blockDim.x + threadIdx.x;
    if (i < N_NODES) g_deg[i] = 0;
}

__global__ void hist_kernel(const int* __restrict__ ei) {
    __shared__ int s_is64;
    int is64 = block_detect_is64(ei, &s_is64);
    int e = blockIdx.x * blockDim.x + threadIdx.x;
    if (e >= N_EDGES) return;
    atomicAdd(&g_deg[edge_dst(ei, e, is64)], 1);
}

__global__ void block_sum_kernel() {
    __shared__ int wsum[32];
    int i = blockIdx.x * 1024 + threadIdx.x;
    int v = (i < N_NODES) ? g_deg[i] : 0;
    int lane = threadIdx.x & 31, w = threadIdx.x >> 5;
#pragma unroll
    for (int o = 16; o > 0; o >>= 1) v += __shfl_xor_sync(0xffffffffu, v, o);
    if (lane == 0) wsum[w] = v;
    __syncthreads();
    if (w == 0) {
        int s = wsum[lane];
#pragma unroll
        for (int o = 16; o > 0; o >>= 1) s += __shfl_xor_sync(0xffffffffu, s, o);
        if (lane == 0) g_bsum[blockIdx.x] = s;
    }
}

// local scan; each block redundantly computes its global offset from g_bsum
__global__ void local_scan_kernel() {
    __shared__ int sb[64];
    __shared__ int wsum[32];
    int t = threadIdx.x;
    if (t < 64) sb[t] = (t < NB) ? g_bsum[t] : 0;
    __syncthreads();
#pragma unroll
    for (int s = 1; s < 64; s <<= 1) {
        int u = 0;
        if (t < 64 && t >= s) u = sb[t - s];
        __syncthreads();
        if (t < 64) sb[t] += u;
        __syncthreads();
    }
    int boff = (blockIdx.x > 0) ? sb[blockIdx.x - 1] : 0;

    int i = blockIdx.x * 1024 + t;
    int v = (i < N_NODES) ? g_deg[i] : 0;
    int lane = t & 31, w = t >> 5;
    int incl = v;
#pragma unroll
    for (int o = 1; o < 32; o <<= 1) {
        int u = __shfl_up_sync(0xffffffffu, incl, o);
        if (lane >= o) incl += u;
    }
    if (lane == 31) wsum[w] = incl;
    __syncthreads();
    if (w == 0) {
        int s = wsum[lane];
#pragma unroll
        for (int o = 1; o < 32; o <<= 1) {
            int u = __shfl_up_sync(0xffffffffu, s, o);
            if (lane >= o) s += u;
        }
        wsum[lane] = s;
    }
    __syncthreads();
    int add = ((w > 0) ? wsum[w - 1] : 0) + boff;
    incl += add;
    if (i < N_NODES) {
        g_off[i + 1] = incl;
        g_cur[i]     = incl - v;
    }
    if (i == 0) g_off[0] = 0;
}

__global__ void scatter_kernel(const int* __restrict__ ei) {
    __shared__ int s_is64;
    int is64 = block_detect_is64(ei, &s_is64);
    int e = blockIdx.x * blockDim.x + threadIdx.x;
    if (e >= N_EDGES) return;
    int d = edge_dst(ei, e, is64);
    int s = edge_src(ei, e, is64);
    int p = atomicAdd(&g_cur[d], 1);
    g_csr[p] = s;
}

// ---------------- 3xTF32 tensor-core GEMM: Y[M,N](fp16) = X[M,K](fp32) @ W[K,N] ----------------
__device__ __forceinline__ uint32_t f2tf32(float f) {
    uint32_t r;
    asm("cvt.rna.tf32.f32 %0, %1;" : "=r"(r) : "f"(f));
    return r;
}

__device__ __forceinline__ void mma8(float c[4], const uint32_t a[4],
                                     uint32_t b0, uint32_t b1) {
    asm volatile(
        "mma.sync.aligned.m16n8k8.row.col.f32.tf32.tf32.f32 "
        "{%0,%1,%2,%3}, {%4,%5,%6,%7}, {%8,%9}, {%0,%1,%2,%3};"
        : "+f"(c[0]), "+f"(c[1]), "+f"(c[2]), "+f"(c[3])
        : "r"(a[0]), "r"(a[1]), "r"(a[2]), "r"(a[3]), "r"(b0), "r"(b1));
}

template <int K, int N>
__global__ void __launch_bounds__(256) mma_gemm_kernel(
        const float* __restrict__ X, const float* __restrict__ W,
        __half* __restrict__ Y) {
    constexpr int NT  = N / 8;
    constexpr int PAD = (8 - (N % 32) + 32) % 32;
    constexpr int PS  = N + PAD;
    extern __shared__ uint32_t smem[];
    uint32_t* sHi = smem;
    uint32_t* sLo = smem + K * PS;

    int tid = threadIdx.x;
    for (int i = tid; i < K * N; i += 256) {
        int k = i / N, n = i % N;
        float w = __ldg(W + i);
        uint32_t hi = f2tf32(w);
        sHi[k * PS + n] = hi;
        sLo[k * PS + n] = f2tf32(w - __uint_as_float(hi));
    }
    __syncthreads();

    int warp = tid >> 5, lane = tid & 31;
    int tig = lane & 3, grp = lane >> 2;
    int row0 = blockIdx.x * 128 + warp * 16;
    int r0 = row0 + grp, r1 = row0 + grp + 8;
    const float* xr0 = X + (size_t)((r0 < N_NODES) ? r0 : (N_NODES - 1)) * K;
    const float* xr1 = X + (size_t)((r1 < N_NODES) ? r1 : (N_NODES - 1)) * K;

    float c[NT][4];
#pragma unroll
    for (int nt = 0; nt < NT; nt++)
#pragma unroll
        for (int j = 0; j < 4; j++) c[nt][j] = 0.f;

#pragma unroll 1
    for (int k0 = 0; k0 < K; k0 += 8) {
        float a0 = __ldg(xr0 + k0 + tig);
        float a1 = __ldg(xr1 + k0 + tig);
        float a2 = __ldg(xr0 + k0 + tig + 4);
        float a3 = __ldg(xr1 + k0 + tig + 4);
        uint32_t ahi[4] = {f2tf32(a0), f2tf32(a1), f2tf32(a2), f2tf32(a3)};
        uint32_t alo[4] = {f2tf32(a0 - __uint_as_float(ahi[0])),
                           f2tf32(a1 - __uint_as_float(ahi[1])),
                           f2tf32(a2 - __uint_as_float(ahi[2])),
                           f2tf32(a3 - __uint_as_float(ahi[3]))};
        const uint32_t* rHi0 = sHi + (k0 + tig) * PS + grp;
        const uint32_t* rHi1 = sHi + (k0 + tig + 4) * PS + grp;
        const uint32_t* rLo0 = sLo + (k0 + tig) * PS + grp;
        const uint32_t* rLo1 = sLo + (k0 + tig + 4) * PS + grp;
#pragma unroll
        for (int nt = 0; nt < NT; nt++) {
            uint32_t b0h = rHi0[nt * 8], b1h = rHi1[nt * 8];
            uint32_t b0l = rLo0[nt * 8], b1l = rLo1[nt * 8];
            mma8(c[nt], ahi, b0h, b1h);   // hi*hi
            mma8(c[nt], alo, b0h, b1h);   // lo*hi
            mma8(c[nt], ahi, b0l, b1l);   // hi*lo
        }
    }

#pragma unroll
    for (int nt = 0; nt < NT; nt++) {
        int col = nt * 8 + 2 * tig;
        if (r0 < N_NODES)
            *(__half2*)(Y + (size_t)r0 * N + col) = __floats2half2_rn(c[nt][0], c[nt][1]);
        if (r1 < N_NODES)
            *(__half2*)(Y + (size_t)r1 * N + col) = __floats2half2_rn(c[nt][2], c[nt][3]);
    }
}

// ---------------- gather aggregation (fp16 in, fp32 accum) + fused epilogue ----------------
__device__ __forceinline__ void acc_h4(float4& acc, uint2 v) {
    float2 f0 = __half22float2(*reinterpret_cast<__half2*>(&v.x));
    float2 f1 = __half22float2(*reinterpret_cast<__half2*>(&v.y));
    acc.x += f0.x; acc.y += f0.y; acc.z += f1.x; acc.w += f1.y;
}

// EPI 0: relu(acc + bias) -> fp32   EPI 1: log_softmax(acc + bias) -> fp32
template <int D, int EPI>
__global__ void agg_kernel(const __half* __restrict__ xin, const float* __restrict__ bias,
                           float* __restrict__ xout) {
    int gw   = (blockIdx.x * blockDim.x + threadIdx.x) >> 5;
    int lane = threadIdx.x & 31;
    if (gw >= N_NODES) return;
    constexpr int D4 = D / 4;
    float4 acc = make_float4(0.f, 0.f, 0.f, 0.f);
    int beg = g_off[gw], end = g_off[gw + 1];
    int e = beg;
    for (; e + 3 < end; e += 4) {
        int s0 = g_csr[e], s1 = g_csr[e + 1], s2 = g_csr[e + 2], s3 = g_csr[e + 3];
        if (lane < D4) {
            uint2 v0 = __ldg((const uint2*)(xin + (size_t)s0 * D) + lane);
            uint2 v1 = __ldg((const uint2*)(xin + (size_t)s1 * D) + lane);
            uint2 v2 = __ldg((const uint2*)(xin + (size_t)s2 * D) + lane);
            uint2 v3 = __ldg((const uint2*)(xin + (size_t)s3 * D) + lane);
            acc_h4(acc, v0);
            acc_h4(acc, v1);
            acc_h4(acc, v2);
            acc_h4(acc, v3);
        }
    }
    for (; e < end; e++) {
        int s0 = g_csr[e];
        if (lane < D4) {
            uint2 v = __ldg((const uint2*)(xin + (size_t)s0 * D) + lane);
            acc_h4(acc, v);
        }
    }
    float4 bb = (lane < D4) ? ((const float4*)bias)[lane] : make_float4(0.f, 0.f, 0.f, 0.f);
    acc.x += bb.x; acc.y += bb.y; acc.z += bb.z; acc.w += bb.w;

    if (EPI == 0) {
        if (lane < D4) {
            acc.x = fmaxf(acc.x, 0.f); acc.y = fmaxf(acc.y, 0.f);
            acc.z = fmaxf(acc.z, 0.f); acc.w = fmaxf(acc.w, 0.f);
            ((float4*)(xout + (size_t)gw * D))[lane] = acc;
        }
    } else {
        float m = (lane < D4)
                ? fmaxf(fmaxf(acc.x, acc.y), fmaxf(acc.z, acc.w))
                : -INFINITY;
#pragma unroll
        for (int o = 16; o > 0; o >>= 1) m = fmaxf(m, __shfl_xor_sync(0xffffffffu, m, o));
        float s = (lane < D4)
                ? (expf(acc.x - m) + expf(acc.y - m)) + (expf(acc.z - m) + expf(acc.w - m))
                : 0.f;
#pragma unroll
        for (int o = 16; o > 0; o >>= 1) s += __shfl_xor_sync(0xffffffffu, s, o);
        float l = m + logf(s);
        if (lane < D4) {
            acc.x -= l; acc.y -= l; acc.z -= l; acc.w -= l;
            ((float4*)(xout + (size_t)gw * D))[lane] = acc;
        }
    }
}

// ---------------- launch ----------------
extern "C" void kernel_launch(void* const* d_in, const int* in_sizes, int n_in,
                              void* d_out, int out_size) {
    const float* x  = (const float*)d_in[0];
    const float* W1 = (const float*)d_in[1];
    const float* b1 = (const float*)d_in[2];
    const float* W2 = (const float*)d_in[3];
    const float* b2 = (const float*)d_in[4];
    const float* W3 = (const float*)d_in[5];
    const float* b3 = (const float*)d_in[6];
    const int*   ei = (const int*)d_in[7];
    float* out = (float*)d_out;

    __half *p_t1, *p_t2, *p_t3;
    float *p_h1, *p_h2;
    cudaGetSymbolAddress((void**)&p_t1, g_t1);
    cudaGetSymbolAddress((void**)&p_h1, g_h1);
    cudaGetSymbolAddress((void**)&p_t2, g_t2);
    cudaGetSymbolAddress((void**)&p_h2, g_h2);
    cudaGetSymbolAddress((void**)&p_t3, g_t3);

    constexpr int PS1 = F1 + ((8 - (F1 % 32) + 32) % 32);   // 104
    constexpr int PS2 = F2 + ((8 - (F2 % 32) + 32) % 32);   // 104
    constexpr int PS3 = F3 + ((8 - (F3 % 32) + 32) % 32);   // 40
    const int smem1 = 2 * F0 * PS1 * 4;
    const int smem2 = 2 * F1 * PS2 * 4;
    const int smem3 = 2 * F2 * PS3 * 4;

    static cudaStream_t s2 = nullptr;
    static cudaEvent_t ev_fork = nullptr, ev_join = nullptr;
    if (!s2) {
        cudaStreamCreateWithFlags(&s2, cudaStreamNonBlocking);
        cudaEventCreateWithFlags(&ev_fork, cudaEventDisableTiming);
        cudaEventCreateWithFlags(&ev_join, cudaEventDisableTiming);
        cudaFuncSetAttribute(mma_gemm_kernel<F0, F1>,
                             cudaFuncAttributeMaxDynamicSharedMemorySize, smem1);
        cudaFuncSetAttribute(mma_gemm_kernel<F1, F2>,
                             cudaFuncAttributeMaxDynamicSharedMemorySize, smem2);
        cudaFuncSetAttribute(mma_gemm_kernel<F2, F3>,
                             cudaFuncAttributeMaxDynamicSharedMemorySize, smem3);
    }

    // fork: CSR build chain on s2, concurrent with GEMM1 on the main stream
    cudaEventRecord(ev_fork, 0);
    cudaStreamWaitEvent(s2, ev_fork, 0);

    zero_deg_kernel<<<(N_NODES + 255) / 256, 256, 0, s2>>>();
    hist_kernel<<<(N_EDGES + 255) / 256, 256, 0, s2>>>(ei);
    block_sum_kernel<<<NB, 1024, 0, s2>>>();
    local_scan_kernel<<<NB, 1024, 0, s2>>>();
    scatter_kernel<<<(N_EDGES + 255) / 256, 256, 0, s2>>>(ei);
    cudaEventRecord(ev_join, s2);

    const int agg_grid  = (N_NODES * 32 + 255) / 256;
    const int gemm_grid = (N_NODES + 127) / 128;

    // main stream: t1 = x @ W1 (independent of CSR)
    mma_gemm_kernel<F0, F1><<<gemm_grid, 256, smem1>>>(x, W1, p_t1);

    // join: aggregation needs CSR
    cudaStreamWaitEvent(0, ev_join, 0);

    // layer 1: h1 = relu(agg(t1) + b1)
    agg_kernel<F1, 0><<<agg_grid, 256>>>(p_t1, b1, p_h1);
    // layer 2
    mma_gemm_kernel<F1, F2><<<gemm_grid, 256, smem2>>>(p_h1, W2, p_t2);
    agg_kernel<F2, 0><<<agg_grid, 256>>>(p_t2, b2, p_h2);
    // layer 3 + log_softmax
    mma_gemm_kernel<F2, F3><<<gemm_grid, 256, smem3>>>(p_h2, W3, p_t3);
    agg_kernel<F3, 1><<<agg_grid, 256>>>(p_t3, b3, out);
}

// round 8
// speedup vs baseline: 1.7732x; 1.0314x over previous
#include <cuda_runtime.h>
#include <cuda_fp16.h>
#include <math.h>
#include <stdint.h>

#define N_NODES 50000
#define N_EDGES 800000
#define F0 128
#define F1 96
#define F2 96
#define F3 40
#define NBLK 74
#define CSR_THREADS 1024
#define CHUNK ((N_NODES + NBLK - 1) / NBLK)   // 676

// ---------------- scratch (static device globals; no allocation) ----------------
__device__ int    g_deg[N_NODES];
__device__ int    g_cur[N_NODES];
__device__ int    g_off[N_NODES + 1];
__device__ int    g_csr[N_EDGES];
__device__ int    g_bsum[NBLK];
__device__ int    g_barrier_ctr;   // reset to 0 at end of every CSR kernel run
__device__ int    g_done_ctr;
__device__ __half g_t1[(size_t)N_NODES * F1];   // x @ W1   (fp16)
__device__ float  g_h1[(size_t)N_NODES * F1];   // relu(agg(t1)+b1)
__device__ __half g_t2[(size_t)N_NODES * F2];   // h1 @ W2  (fp16)
__device__ float  g_h2[(size_t)N_NODES * F2];   // relu(agg(t2)+b2)
__device__ __half g_t3[(size_t)N_NODES * F3];   // h2 @ W3  (fp16)

// ---------------- edge index access ----------------
__device__ __forceinline__ int edge_src(const int* ei, int e, int is64) {
    return is64 ? ei[2 * e] : ei[e];
}
__device__ __forceinline__ int edge_dst(const int* ei, int e, int is64) {
    return is64 ? ei[2 * (N_EDGES + e)] : ei[N_EDGES + e];
}

// ---------------- software grid barrier (74 co-resident blocks) ----------------
__device__ __forceinline__ void grid_barrier(int phase) {
    __syncthreads();
    if (threadIdx.x == 0) {
        __threadfence();                       // release prior writes
        atomicAdd(&g_barrier_ctr, 1);
        int target = phase * NBLK;
        while ((*(volatile int*)&g_barrier_ctr) - target < 0)
            __nanosleep(64);
    }
    __syncthreads();
    __threadfence();                           // acquire
}

// ---------------- single persistent CSR-build kernel ----------------
__global__ void __launch_bounds__(CSR_THREADS) csr_build_kernel(const int* __restrict__ ei) {
    __shared__ int s_is64;
    __shared__ int s_boff;
    __shared__ int wsum[32];

    int tid  = threadIdx.x;
    int lane = tid & 31, w = tid >> 5;
    int gtid = blockIdx.x * CSR_THREADS + tid;
    constexpr int NT = NBLK * CSR_THREADS;

    // dtype detect (read-only, no ordering needed)
    if (tid < 32) {
        int acc = 0;
#pragma unroll
        for (int j = 0; j < 4; j++) acc |= ei[1 + 2 * (tid * 4 + j)];
#pragma unroll
        for (int o = 16; o > 0; o >>= 1) acc |= __shfl_xor_sync(0xffffffffu, acc, o);
        if (tid == 0) s_is64 = (acc == 0) ? 1 : 0;
    }
    __syncthreads();
    int is64 = s_is64;

    // P0: zero degrees
    for (int i = gtid; i < N_NODES; i += NT) g_deg[i] = 0;
    grid_barrier(1);

    // P1: histogram of dst
    for (int e = gtid; e < N_EDGES; e += NT)
        atomicAdd(&g_deg[edge_dst(ei, e, is64)], 1);
    grid_barrier(2);

    // P2: per-block chunk sum
    int cbase = blockIdx.x * CHUNK;
    int i0 = cbase + tid;
    int v = (tid < CHUNK && i0 < N_NODES) ? g_deg[i0] : 0;
    {
        int s = v;
#pragma unroll
        for (int o = 16; o > 0; o >>= 1) s += __shfl_xor_sync(0xffffffffu, s, o);
        if (lane == 0) wsum[w] = s;
        __syncthreads();
        if (w == 0) {
            int t = wsum[lane];
#pragma unroll
            for (int o = 16; o > 0; o >>= 1) t += __shfl_xor_sync(0xffffffffu, t, o);
            if (lane == 0) g_bsum[blockIdx.x] = t;
        }
    }
    grid_barrier(3);

    // P3: scan — block offset from bsums (serial by thread 0, 74 adds), then block scan
    if (tid == 0) {
        int s = 0;
        for (int b = 0; b < (int)blockIdx.x; b++) s += g_bsum[b];
        s_boff = s;
    }
    __syncthreads();
    {
        int incl = v;
#pragma unroll
        for (int o = 1; o < 32; o <<= 1) {
            int u = __shfl_up_sync(0xffffffffu, incl, o);
            if (lane >= o) incl += u;
        }
        if (lane == 31) wsum[w] = incl;
        __syncthreads();
        if (w == 0) {
            int s = wsum[lane];
#pragma unroll
            for (int o = 1; o < 32; o <<= 1) {
                int u = __shfl_up_sync(0xffffffffu, s, o);
                if (lane >= o) s += u;
            }
            wsum[lane] = s;
        }
        __syncthreads();
        incl += ((w > 0) ? wsum[w - 1] : 0) + s_boff;
        if (tid < CHUNK && i0 < N_NODES) {
            g_off[i0 + 1] = incl;
            g_cur[i0]     = incl - v;
        }
        if (blockIdx.x == 0 && tid == 0) g_off[0] = 0;
    }
    grid_barrier(4);

    // P4: scatter src into CSR slots
    for (int e = gtid; e < N_EDGES; e += NT) {
        int d = edge_dst(ei, e, is64);
        int s = edge_src(ei, e, is64);
        int p = atomicAdd(&g_cur[d], 1);
        g_csr[p] = s;
    }

    // reset barrier counters for the next (identical) replay
    __syncthreads();
    if (tid == 0) {
        __threadfence();
        int d = atomicAdd(&g_done_ctr, 1);
        if (d == NBLK - 1) {
            g_barrier_ctr = 0;
            g_done_ctr = 0;
            __threadfence();
        }
    }
}

// ---------------- 3xTF32 tensor-core GEMM: Y[M,N](fp16) = X[M,K](fp32) @ W[K,N] ----------------
__device__ __forceinline__ uint32_t f2tf32(float f) {
    uint32_t r;
    asm("cvt.rna.tf32.f32 %0, %1;" : "=r"(r) : "f"(f));
    return r;
}

__device__ __forceinline__ void mma8(float c[4], const uint32_t a[4],
                                     uint32_t b0, uint32_t b1) {
    asm volatile(
        "mma.sync.aligned.m16n8k8.row.col.f32.tf32.tf32.f32 "
        "{%0,%1,%2,%3}, {%4,%5,%6,%7}, {%8,%9}, {%0,%1,%2,%3};"
        : "+f"(c[0]), "+f"(c[1]), "+f"(c[2]), "+f"(c[3])
        : "r"(a[0]), "r"(a[1]), "r"(a[2]), "r"(a[3]), "r"(b0), "r"(b1));
}

template <int K, int N>
__global__ void __launch_bounds__(256) mma_gemm_kernel(
        const float* __restrict__ X, const float* __restrict__ W,
        __half* __restrict__ Y) {
    constexpr int NT  = N / 8;
    constexpr int PAD = (8 - (N % 32) + 32) % 32;
    constexpr int PS  = N + PAD;
    extern __shared__ uint32_t smem[];
    uint32_t* sHi = smem;
    uint32_t* sLo = smem + K * PS;

    int tid = threadIdx.x;
    for (int i = tid; i < K * N; i += 256) {
        int k = i / N, n = i % N;
        float w = __ldg(W + i);
        uint32_t hi = f2tf32(w);
        sHi[k * PS + n] = hi;
        sLo[k * PS + n] = f2tf32(w - __uint_as_float(hi));
    }
    __syncthreads();

    int warp = tid >> 5, lane = tid & 31;
    int tig = lane & 3, grp = lane >> 2;
    int row0 = blockIdx.x * 128 + warp * 16;
    int r0 = row0 + grp, r1 = row0 + grp + 8;
    const float* xr0 = X + (size_t)((r0 < N_NODES) ? r0 : (N_NODES - 1)) * K;
    const float* xr1 = X + (size_t)((r1 < N_NODES) ? r1 : (N_NODES - 1)) * K;

    float c[NT][4];
#pragma unroll
    for (int nt = 0; nt < NT; nt++)
#pragma unroll
        for (int j = 0; j < 4; j++) c[nt][j] = 0.f;

#pragma unroll 1
    for (int k0 = 0; k0 < K; k0 += 8) {
        float a0 = __ldg(xr0 + k0 + tig);
        float a1 = __ldg(xr1 + k0 + tig);
        float a2 = __ldg(xr0 + k0 + tig + 4);
        float a3 = __ldg(xr1 + k0 + tig + 4);
        uint32_t ahi[4] = {f2tf32(a0), f2tf32(a1), f2tf32(a2), f2tf32(a3)};
        uint32_t alo[4] = {f2tf32(a0 - __uint_as_float(ahi[0])),
                           f2tf32(a1 - __uint_as_float(ahi[1])),
                           f2tf32(a2 - __uint_as_float(ahi[2])),
                           f2tf32(a3 - __uint_as_float(ahi[3]))};
        const uint32_t* rHi0 = sHi + (k0 + tig) * PS + grp;
        const uint32_t* rHi1 = sHi + (k0 + tig + 4) * PS + grp;
        const uint32_t* rLo0 = sLo + (k0 + tig) * PS + grp;
        const uint32_t* rLo1 = sLo + (k0 + tig + 4) * PS + grp;
#pragma unroll
        for (int nt = 0; nt < NT; nt++) {
            uint32_t b0h = rHi0[nt * 8], b1h = rHi1[nt * 8];
            uint32_t b0l = rLo0[nt * 8], b1l = rLo1[nt * 8];
            mma8(c[nt], ahi, b0h, b1h);   // hi*hi
            mma8(c[nt], alo, b0h, b1h);   // lo*hi
            mma8(c[nt], ahi, b0l, b1l);   // hi*lo
        }
    }

#pragma unroll
    for (int nt = 0; nt < NT; nt++) {
        int col = nt * 8 + 2 * tig;
        if (r0 < N_NODES)
            *(__half2*)(Y + (size_t)r0 * N + col) = __floats2half2_rn(c[nt][0], c[nt][1]);
        if (r1 < N_NODES)
            *(__half2*)(Y + (size_t)r1 * N + col) = __floats2half2_rn(c[nt][2], c[nt][3]);
    }
}

// ---------------- gather aggregation (fp16 in, fp32 accum) + fused epilogue ----------------
__device__ __forceinline__ void acc_h4(float4& acc, uint2 v) {
    float2 f0 = __half22float2(*reinterpret_cast<__half2*>(&v.x));
    float2 f1 = __half22float2(*reinterpret_cast<__half2*>(&v.y));
    acc.x += f0.x; acc.y += f0.y; acc.z += f1.x; acc.w += f1.y;
}

// EPI 0: relu(acc + bias) -> fp32   EPI 1: log_softmax(acc + bias) -> fp32
template <int D, int EPI>
__global__ void agg_kernel(const __half* __restrict__ xin, const float* __restrict__ bias,
                           float* __restrict__ xout) {
    int gw   = (blockIdx.x * blockDim.x + threadIdx.x) >> 5;
    int lane = threadIdx.x & 31;
    if (gw >= N_NODES) return;
    constexpr int D4 = D / 4;
    float4 acc = make_float4(0.f, 0.f, 0.f, 0.f);
    int beg = g_off[gw], end = g_off[gw + 1];
    int e = beg;
    for (; e + 3 < end; e += 4) {
        int s0 = g_csr[e], s1 = g_csr[e + 1], s2 = g_csr[e + 2], s3 = g_csr[e + 3];
        if (lane < D4) {
            uint2 v0 = __ldg((const uint2*)(xin + (size_t)s0 * D) + lane);
            uint2 v1 = __ldg((const uint2*)(xin + (size_t)s1 * D) + lane);
            uint2 v2 = __ldg((const uint2*)(xin + (size_t)s2 * D) + lane);
            uint2 v3 = __ldg((const uint2*)(xin + (size_t)s3 * D) + lane);
            acc_h4(acc, v0);
            acc_h4(acc, v1);
            acc_h4(acc, v2);
            acc_h4(acc, v3);
        }
    }
    for (; e < end; e++) {
        int s0 = g_csr[e];
        if (lane < D4) {
            uint2 v = __ldg((const uint2*)(xin + (size_t)s0 * D) + lane);
            acc_h4(acc, v);
        }
    }
    float4 bb = (lane < D4) ? ((const float4*)bias)[lane] : make_float4(0.f, 0.f, 0.f, 0.f);
    acc.x += bb.x; acc.y += bb.y; acc.z += bb.z; acc.w += bb.w;

    if (EPI == 0) {
        if (lane < D4) {
            acc.x = fmaxf(acc.x, 0.f); acc.y = fmaxf(acc.y, 0.f);
            acc.z = fmaxf(acc.z, 0.f); acc.w = fmaxf(acc.w, 0.f);
            ((float4*)(xout + (size_t)gw * D))[lane] = acc;
        }
    } else {
        float m = (lane < D4)
                ? fmaxf(fmaxf(acc.x, acc.y), fmaxf(acc.z, acc.w))
                : -INFINITY;
#pragma unroll
        for (int o = 16; o > 0; o >>= 1) m = fmaxf(m, __shfl_xor_sync(0xffffffffu, m, o));
        float s = (lane < D4)
                ? (expf(acc.x - m) + expf(acc.y - m)) + (expf(acc.z - m) + expf(acc.w - m))
                : 0.f;
#pragma unroll
        for (int o = 16; o > 0; o >>= 1) s += __shfl_xor_sync(0xffffffffu, s, o);
        float l = m + logf(s);
        if (lane < D4) {
            acc.x -= l; acc.y -= l; acc.z -= l; acc.w -= l;
            ((float4*)(xout + (size_t)gw * D))[lane] = acc;
        }
    }
}

// ---------------- launch ----------------
extern "C" void kernel_launch(void* const* d_in, const int* in_sizes, int n_in,
                              void* d_out, int out_size) {
    const float* x  = (const float*)d_in[0];
    const float* W1 = (const float*)d_in[1];
    const float* b1 = (const float*)d_in[2];
    const float* W2 = (const float*)d_in[3];
    const float* b2 = (const float*)d_in[4];
    const float* W3 = (const float*)d_in[5];
    const float* b3 = (const float*)d_in[6];
    const int*   ei = (const int*)d_in[7];
    float* out = (float*)d_out;

    __half *p_t1, *p_t2, *p_t3;
    float *p_h1, *p_h2;
    cudaGetSymbolAddress((void**)&p_t1, g_t1);
    cudaGetSymbolAddress((void**)&p_h1, g_h1);
    cudaGetSymbolAddress((void**)&p_t2, g_t2);
    cudaGetSymbolAddress((void**)&p_h2, g_h2);
    cudaGetSymbolAddress((void**)&p_t3, g_t3);

    constexpr int PS1 = F1 + ((8 - (F1 % 32) + 32) % 32);   // 104
    constexpr int PS2 = F2 + ((8 - (F2 % 32) + 32) % 32);   // 104
    constexpr int PS3 = F3 + ((8 - (F3 % 32) + 32) % 32);   // 40
    const int smem1 = 2 * F0 * PS1 * 4;
    const int smem2 = 2 * F1 * PS2 * 4;
    const int smem3 = 2 * F2 * PS3 * 4;

    static cudaStream_t s2 = nullptr;
    static cudaEvent_t ev_fork = nullptr, ev_join = nullptr;
    if (!s2) {
        cudaStreamCreateWithFlags(&s2, cudaStreamNonBlocking);
        cudaEventCreateWithFlags(&ev_fork, cudaEventDisableTiming);
        cudaEventCreateWithFlags(&ev_join, cudaEventDisableTiming);
        cudaFuncSetAttribute(mma_gemm_kernel<F0, F1>,
                             cudaFuncAttributeMaxDynamicSharedMemorySize, smem1);
        cudaFuncSetAttribute(mma_gemm_kernel<F1, F2>,
                             cudaFuncAttributeMaxDynamicSharedMemorySize, smem2);
        cudaFuncSetAttribute(mma_gemm_kernel<F2, F3>,
                             cudaFuncAttributeMaxDynamicSharedMemorySize, smem3);
    }

    // fork: persistent CSR build on s2 (74 blocks = half chip), GEMM1 on main stream
    cudaEventRecord(ev_fork, 0);
    cudaStreamWaitEvent(s2, ev_fork, 0);
    csr_build_kernel<<<NBLK, CSR_THREADS, 0, s2>>>(ei);
    cudaEventRecord(ev_join, s2);

    const int agg_grid  = (N_NODES * 32 + 255) / 256;
    const int gemm_grid = (N_NODES + 127) / 128;

    // main stream: t1 = x @ W1 (independent of CSR)
    mma_gemm_kernel<F0, F1><<<gemm_grid, 256, smem1>>>(x, W1, p_t1);

    // join: aggregation needs CSR
    cudaStreamWaitEvent(0, ev_join, 0);

    // layer 1: h1 = relu(agg(t1) + b1)
    agg_kernel<F1, 0><<<agg_grid, 256>>>(p_t1, b1, p_h1);
    // layer 2
    mma_gemm_kernel<F1, F2><<<gemm_grid, 256, smem2>>>(p_h1, W2, p_t2);
    agg_kernel<F2, 0><<<agg_grid, 256>>>(p_t2, b2, p_h2);
    // layer 3 + log_softmax
    mma_gemm_kernel<F2, F3><<<gemm_grid, 256, smem3>>>(p_h2, W3, p_t3);
    agg_kernel<F3, 1><<<agg_grid, 256>>>(p_t3, b3, out);
}